// round 1
// baseline (speedup 1.0000x reference)
#include <cuda_runtime.h>
#include <cuda_bf16.h>
#include <math.h>

// ---------------- problem constants ----------------
#define SZ    2048      // source nodes
#define NN    10        // neighbors
#define DD    172       // embedding dim
#define EDGE_ 172
#define TDIM  100
#define EE    272       // D + TD
#define KDIM  444       // D + EDGE + TD
#define KDT   4440      // KDIM * N
#define HH    2
#define HDIM  136
#define M0    (SZ*NN)   // 20480
#define NKV   544       // 272 kp | 272 vp

// output layout (floats)
#define OUT_R0 0
#define OUT_R1 3522560
#define OUT_E1 3874816
#define OUT_T1 7397376

// ---------------- scratch (static device memory; no allocations) ----------------
__device__ float g_qp0 [M0*EE];
__device__ float g_kvp0[M0*NKV];
__device__ float g_attn0[M0*EE];
__device__ float g_a0  [M0*EE];
__device__ float g_h0  [M0*DD];
__device__ float g_qp1 [SZ*EE];
__device__ float g_kvp1[SZ*NKV];
__device__ float g_scores[2u*2048u*2048u];
__device__ float g_vT  [2*HDIM*SZ];
__device__ float g_attn1[SZ*EE];
__device__ float g_a1  [SZ*EE];
__device__ float g_h1  [SZ*DD];
__device__ float g_Wkv [NKV*KDT];
__device__ float g_bkv [NKV];

static inline int cdiv(int a, int b) { return (a + b - 1) / b; }

// ---------------- A-operand gather (all float4-safe: every segment boundary %4==0) ----
// AK=0 plain [lda,aoff]; AK=1 TGN neighbor concat; AK=2 Q concat (emb|td or zeros);
// AK=3 FFN concat (attn 272 | emb 172)
template<int AK>
__device__ __forceinline__ float4 loadA4(const float* __restrict__ p0,
                                         const float* __restrict__ p1,
                                         const float* __restrict__ p2,
                                         int lda, int aoff, int row, int k4)
{
    if (AK == 0) {
        return *reinterpret_cast<const float4*>(p0 + (size_t)row*lda + aoff + k4);
    } else if (AK == 1) {
        int j = k4 / KDIM;
        int c = k4 - j*KDIM;
        int nb = row*NN + j;
        const float* p;
        if (c < DD)            p = p0 + (size_t)nb*DD   + c;
        else if (c < DD+EDGE_) p = p1 + (size_t)nb*EDGE_ + (c-DD);
        else                   p = p2 + (size_t)nb*TDIM + (c-DD-EDGE_);
        return *reinterpret_cast<const float4*>(p);
    } else if (AK == 2) {
        if (k4 < DD) return *reinterpret_cast<const float4*>(p0 + (size_t)row*DD + k4);
        if (p1)      return *reinterpret_cast<const float4*>(p1 + (size_t)row*TDIM + (k4-DD));
        return make_float4(0.f,0.f,0.f,0.f);
    } else { // AK == 3
        if (k4 < EE) return *reinterpret_cast<const float4*>(p0 + (size_t)row*EE + k4);
        return *reinterpret_cast<const float4*>(p1 + (size_t)row*DD + (k4-EE));
    }
}

// ---------------- generic NT SGEMM: C[m,n] = (sum_k A[m,k]*W[n,k] + bias[n])*scale ----
// BM=128 BN=64 BK=8, 256 threads, 8x4 per thread.
template<int AK>
__global__ __launch_bounds__(256)
void gemm_k(const float* __restrict__ p0, const float* __restrict__ p1,
            const float* __restrict__ p2, int lda, int aoff,
            const float* __restrict__ W, int ldw, int woff,
            const float* __restrict__ bias,
            float* __restrict__ C, int ldc, int coff,
            int M, int N, int K, float scale, int relu)
{
    __shared__ float As[8][128];
    __shared__ float Ws[8][64];

    const int tid  = threadIdx.x;
    const int row0 = blockIdx.y * 128;
    const int n0   = blockIdx.x * 64;
    const int arow = tid >> 1, akq = tid & 1;
    const int wn   = tid >> 1, wkq = tid & 1;   // tid < 128 only
    const int tx   = tid & 15, ty = tid >> 4;

    float acc[8][4];
    #pragma unroll
    for (int i = 0; i < 8; i++)
        #pragma unroll
        for (int j = 0; j < 4; j++) acc[i][j] = 0.f;

    for (int kt = 0; kt < K; kt += 8) {
        {
            int ka = kt + akq*4;
            float4 av = (ka < K) ? loadA4<AK>(p0,p1,p2,lda,aoff,row0+arow,ka)
                                 : make_float4(0.f,0.f,0.f,0.f);
            As[akq*4+0][arow] = av.x;
            As[akq*4+1][arow] = av.y;
            As[akq*4+2][arow] = av.z;
            As[akq*4+3][arow] = av.w;
        }
        if (tid < 128) {
            int kw = kt + wkq*4;
            int n  = n0 + wn;
            float4 wv = (kw < K && n < N)
                ? *reinterpret_cast<const float4*>(W + (size_t)n*ldw + woff + kw)
                : make_float4(0.f,0.f,0.f,0.f);
            Ws[wkq*4+0][wn] = wv.x;
            Ws[wkq*4+1][wn] = wv.y;
            Ws[wkq*4+2][wn] = wv.z;
            Ws[wkq*4+3][wn] = wv.w;
        }
        __syncthreads();
        #pragma unroll
        for (int kk = 0; kk < 8; kk++) {
            float a[8], b[4];
            #pragma unroll
            for (int i = 0; i < 8; i++) a[i] = As[kk][ty*8+i];
            #pragma unroll
            for (int j = 0; j < 4; j++) b[j] = Ws[kk][tx*4+j];
            #pragma unroll
            for (int i = 0; i < 8; i++)
                #pragma unroll
                for (int j = 0; j < 4; j++)
                    acc[i][j] = fmaf(a[i], b[j], acc[i][j]);
        }
        __syncthreads();
    }

    #pragma unroll
    for (int i = 0; i < 8; i++) {
        int row = row0 + ty*8 + i;
        #pragma unroll
        for (int j = 0; j < 4; j++) {
            int col = n0 + tx*4 + j;
            if (row < M && col < N) {
                float v = acc[i][j];
                if (bias) v += bias[col];
                v *= scale;
                if (relu) v = fmaxf(v, 0.f);
                C[(size_t)row*ldc + coff + col] = v;
            }
        }
    }
}

// ---------------- pack Wk|Wv and bk|bv into one operand ----------------
__global__ void pack_wkv_k(const float* __restrict__ Wk, const float* __restrict__ Wv,
                           const float* __restrict__ bk, const float* __restrict__ bv)
{
    int idx = blockIdx.x*256 + threadIdx.x;
    const int tot = NKV*KDT;
    if (idx < tot)
        g_Wkv[idx] = (idx < EE*KDT) ? Wk[idx] : Wv[idx - EE*KDT];
    if (idx < NKV)
        g_bkv[idx] = (idx < EE) ? bk[idx] : bv[idx - EE];
}

// ---------------- propagation-0 attention: per-source 10x10, H=2 ----------------
__global__ __launch_bounds__(256)
void attn0_k(const float* __restrict__ qp, const float* __restrict__ kvp,
             float* __restrict__ out)
{
    __shared__ float sq [NN*EE];    // 2720
    __shared__ float skv[NN*NKV];   // 5440
    __shared__ float sc[2][NN][NN];

    int s = blockIdx.x;
    int tid = threadIdx.x;
    size_t qb = (size_t)s*NN*EE;
    size_t kb = (size_t)s*NN*NKV;

    for (int i = tid; i < NN*EE;  i += 256) sq[i]  = qp[qb + i];
    for (int i = tid; i < NN*NKV; i += 256) skv[i] = kvp[kb + i];
    __syncthreads();

    if (tid < 2*NN*NN) {
        int h = tid / (NN*NN);
        int r = tid - h*NN*NN;
        int i = r / NN, j = r - i*NN;
        int off = h*HDIM;
        const float* q = sq  + i*EE  + off;
        const float* k = skv + j*NKV + off;
        float sum = 0.f;
        #pragma unroll 4
        for (int d = 0; d < HDIM; d++) sum = fmaf(q[d], k[d], sum);
        sc[h][i][j] = sum;
    }
    __syncthreads();

    if (tid < 2*NN) {
        int h = tid / NN, i = tid - h*NN;
        float m = -1e30f;
        #pragma unroll
        for (int j = 0; j < NN; j++) m = fmaxf(m, sc[h][i][j]);
        float ssum = 0.f;
        #pragma unroll
        for (int j = 0; j < NN; j++) {
            float e = expf(sc[h][i][j] - m);
            sc[h][i][j] = e;
            ssum += e;
        }
        float inv = 1.f / ssum;
        #pragma unroll
        for (int j = 0; j < NN; j++) sc[h][i][j] *= inv;
    }
    __syncthreads();

    for (int t = tid; t < NN*EE; t += 256) {
        int i = t / EE, col = t - i*EE;
        int h = (col >= HDIM) ? 1 : 0;
        float sum = 0.f;
        #pragma unroll
        for (int j = 0; j < NN; j++)
            sum = fmaf(sc[h][i][j], skv[j*NKV + EE + col], sum);
        out[qb + t] = sum;
    }
}

// ---------------- row softmax over 2048 (prop 1) ----------------
__global__ __launch_bounds__(256)
void softmax_k(float* __restrict__ p)
{
    __shared__ float red[8];
    size_t base = (size_t)blockIdx.x * 2048;
    int tid = threadIdx.x;

    float v[8];
    float m = -1e30f;
    #pragma unroll
    for (int u = 0; u < 8; u++) {
        v[u] = p[base + tid + u*256];
        m = fmaxf(m, v[u]);
    }
    #pragma unroll
    for (int o = 16; o; o >>= 1) m = fmaxf(m, __shfl_xor_sync(0xffffffffu, m, o));
    if ((tid & 31) == 0) red[tid >> 5] = m;
    __syncthreads();
    float mm = red[0];
    #pragma unroll
    for (int i = 1; i < 8; i++) mm = fmaxf(mm, red[i]);

    float s = 0.f;
    #pragma unroll
    for (int u = 0; u < 8; u++) {
        v[u] = __expf(v[u] - mm);
        s += v[u];
    }
    #pragma unroll
    for (int o = 16; o; o >>= 1) s += __shfl_xor_sync(0xffffffffu, s, o);
    __syncthreads();
    if ((tid & 31) == 0) red[tid >> 5] = s;
    __syncthreads();
    float tot = 0.f;
    #pragma unroll
    for (int i = 0; i < 8; i++) tot += red[i];
    float inv = 1.f / tot;
    #pragma unroll
    for (int u = 0; u < 8; u++) p[base + tid + u*256] = v[u] * inv;
}

// ---------------- transpose vp1 into [h*136+d][2048] for the PV GEMM ----------------
__global__ void transpose_v_k(const float* __restrict__ kvp, float* __restrict__ vT)
{
    int idx = blockIdx.x*256 + threadIdx.x;
    if (idx >= 2*HDIM*SZ) return;
    int j  = idx & 2047;
    int hd = idx >> 11;           // h*136 + d
    vT[idx] = kvp[(size_t)j*NKV + EE + hd];
}

// ---------------- launcher ----------------
extern "C" void kernel_launch(void* const* d_in, const int* in_sizes, int n_in,
                              void* d_out, int out_size)
{
    const float* emb0  = (const float*)d_in[0];
    const float* edge0 = (const float*)d_in[1];
    const float* td0   = (const float*)d_in[2];
    const float* emb1  = (const float*)d_in[3];
    const float* edge1 = (const float*)d_in[4];
    const float* td1   = (const float*)d_in[5];
    const float* emb2  = (const float*)d_in[6];
    const float* Wq = (const float*)d_in[7];
    const float* bq = (const float*)d_in[8];
    const float* Wk = (const float*)d_in[9];
    const float* bk = (const float*)d_in[10];
    const float* Wv = (const float*)d_in[11];
    const float* bv = (const float*)d_in[12];
    const float* Wo = (const float*)d_in[13];
    const float* bo = (const float*)d_in[14];
    const float* W1 = (const float*)d_in[15];
    const float* b1 = (const float*)d_in[16];
    const float* W2 = (const float*)d_in[17];
    const float* b2 = (const float*)d_in[18];
    float* out = (float*)d_out;

    float *qp0, *kvp0, *attn0, *a0, *h0;
    float *qp1, *kvp1, *scores, *vT, *attn1, *a1, *h1, *wkv, *bkv;
    cudaGetSymbolAddress((void**)&qp0,   g_qp0);
    cudaGetSymbolAddress((void**)&kvp0,  g_kvp0);
    cudaGetSymbolAddress((void**)&attn0, g_attn0);
    cudaGetSymbolAddress((void**)&a0,    g_a0);
    cudaGetSymbolAddress((void**)&h0,    g_h0);
    cudaGetSymbolAddress((void**)&qp1,   g_qp1);
    cudaGetSymbolAddress((void**)&kvp1,  g_kvp1);
    cudaGetSymbolAddress((void**)&scores,g_scores);
    cudaGetSymbolAddress((void**)&vT,    g_vT);
    cudaGetSymbolAddress((void**)&attn1, g_attn1);
    cudaGetSymbolAddress((void**)&a1,    g_a1);
    cudaGetSymbolAddress((void**)&h1,    g_h1);
    cudaGetSymbolAddress((void**)&wkv,   g_Wkv);
    cudaGetSymbolAddress((void**)&bkv,   g_bkv);

    const float SCALE = 0.08574929257125441f;  // 1/sqrt(136)

    pack_wkv_k<<<cdiv(NKV*KDT, 256), 256>>>(Wk, Wv, bk, bv);

    // ======== propagation 0 ========
    // qp0 = (concat(emb1,td1) @ Wq^T + bq) * scale            (20480 x 272)
    gemm_k<2><<<dim3(cdiv(EE,64), cdiv(M0,128)), 256>>>(
        emb1, td1, nullptr, 0, 0, Wq, EE, 0, bq, qp0, EE, 0, M0, EE, EE, SCALE, 0);
    // kvp0 = neigh0 @ [Wk|Wv]^T + [bk|bv]                     (20480 x 544)
    gemm_k<1><<<dim3(cdiv(NKV,64), cdiv(M0,128)), 256>>>(
        emb0, edge0, td0, 0, 0, wkv, KDT, 0, bkv, kvp0, NKV, 0, M0, NKV, KDT, 1.f, 0);
    // per-source 10x10 attention
    attn0_k<<<SZ, 256>>>(qp0, kvp0, attn0);
    // a0 = attn0 @ Wo^T + bo
    gemm_k<0><<<dim3(cdiv(EE,64), cdiv(M0,128)), 256>>>(
        attn0, nullptr, nullptr, EE, 0, Wo, EE, 0, bo, a0, EE, 0, M0, EE, EE, 1.f, 0);
    // h0 = relu(concat(a0,emb1) @ W1^T + b1)
    gemm_k<3><<<dim3(cdiv(DD,64), cdiv(M0,128)), 256>>>(
        a0, emb1, nullptr, 0, 0, W1, KDIM, 0, b1, h0, DD, 0, M0, DD, KDIM, 1.f, 1);
    // r0 = h0 @ W2^T + b2  -> out
    gemm_k<0><<<dim3(cdiv(DD,64), cdiv(M0,128)), 256>>>(
        h0, nullptr, nullptr, DD, 0, W2, DD, 0, b2, out + OUT_R0, DD, 0, M0, DD, DD, 1.f, 0);

    // ======== propagation 1 ========
    // qp1 = (concat(emb2, zeros) @ Wq^T + bq) * scale          (2048 x 272)
    gemm_k<2><<<dim3(cdiv(EE,64), cdiv(SZ,128)), 256>>>(
        emb2, nullptr, nullptr, 0, 0, Wq, EE, 0, bq, qp1, EE, 0, SZ, EE, EE, SCALE, 0);
    // kvp1 = neigh1 @ [Wk|Wv]^T + [bk|bv]                      (2048 x 544)
    gemm_k<1><<<dim3(cdiv(NKV,64), cdiv(SZ,128)), 256>>>(
        emb1, edge1, td1, 0, 0, wkv, KDT, 0, bkv, kvp1, NKV, 0, SZ, NKV, KDT, 1.f, 0);
    // scores[h] = qp1[:,h*136:] @ kp1[:,h*136:]^T              (2 x 2048 x 2048)
    for (int h = 0; h < 2; h++) {
        gemm_k<0><<<dim3(cdiv(SZ,64), cdiv(SZ,128)), 256>>>(
            qp1, nullptr, nullptr, EE, h*HDIM, kvp1, NKV, h*HDIM, nullptr,
            scores + (size_t)h*SZ*SZ, SZ, 0, SZ, SZ, HDIM, 1.f, 0);
    }
    softmax_k<<<2*SZ, 256>>>(scores);
    transpose_v_k<<<cdiv(2*HDIM*SZ, 256), 256>>>(kvp1, vT);
    // attn1[:, h*136:] = P[h] @ vp1[:, h*136:]
    for (int h = 0; h < 2; h++) {
        gemm_k<0><<<dim3(cdiv(HDIM,64), cdiv(SZ,128)), 256>>>(
            scores + (size_t)h*SZ*SZ, nullptr, nullptr, SZ, 0,
            vT + (size_t)h*HDIM*SZ, SZ, 0, nullptr,
            attn1, EE, h*HDIM, SZ, HDIM, SZ, 1.f, 0);
    }
    // a1 = attn1 @ Wo^T + bo
    gemm_k<0><<<dim3(cdiv(EE,64), cdiv(SZ,128)), 256>>>(
        attn1, nullptr, nullptr, EE, 0, Wo, EE, 0, bo, a1, EE, 0, SZ, EE, EE, 1.f, 0);
    // h1 = relu(concat(a1,emb2) @ W1^T + b1)
    gemm_k<3><<<dim3(cdiv(DD,64), cdiv(SZ,128)), 256>>>(
        a1, emb2, nullptr, 0, 0, W1, KDIM, 0, b1, h1, DD, 0, SZ, DD, KDIM, 1.f, 1);
    // r1 = h1 @ W2^T + b2 -> out
    gemm_k<0><<<dim3(cdiv(DD,64), cdiv(SZ,128)), 256>>>(
        h1, nullptr, nullptr, DD, 0, W2, DD, 0, b2, out + OUT_R1, DD, 0, SZ, DD, DD, 1.f, 0);

    // ======== pass-through outputs ========
    cudaMemcpyAsync(out + OUT_E1, edge1, (size_t)SZ*NN*EDGE_*sizeof(float),
                    cudaMemcpyDeviceToDevice);
    cudaMemcpyAsync(out + OUT_T1, td1, (size_t)SZ*NN*TDIM*sizeof(float),
                    cudaMemcpyDeviceToDevice);
}

// round 2
// speedup vs baseline: 1.0545x; 1.0545x over previous
#include <cuda_runtime.h>
#include <cuda_bf16.h>
#include <math.h>

// ---------------- problem constants ----------------
#define SZ    2048      // source nodes
#define NN    10        // neighbors
#define DD    172       // embedding dim
#define EDGE_ 172
#define TDIM  100
#define EE    272       // D + TD
#define KDIM  444       // D + EDGE + TD
#define KDT   4440      // KDIM * N
#define HH    2
#define HDIM  136
#define M0    (SZ*NN)   // 20480
#define NKV   544       // 272 kp | 272 vp

// output layout (floats)
#define OUT_R0 0
#define OUT_R1 3522560
#define OUT_E1 3874816
#define OUT_T1 7397376

// ---------------- scratch (static device memory; no allocations) ----------------
__device__ float g_qp0 [M0*EE];
__device__ float g_kvp0[M0*NKV];
__device__ float g_attn0[M0*EE];
__device__ float g_a0  [M0*EE];
__device__ float g_h0  [M0*DD];
__device__ float g_qp1 [SZ*EE];
__device__ float g_kvp1[SZ*NKV];
__device__ float g_scores[2u*2048u*2048u];
__device__ float g_vT  [2*HDIM*SZ];
__device__ float g_attn1[SZ*EE];
__device__ float g_a1  [SZ*EE];
__device__ float g_h1  [SZ*DD];
__device__ float g_Wkv [NKV*KDT];
__device__ float g_bkv [NKV];

static inline int cdiv(int a, int b) { return (a + b - 1) / b; }

// ---------------- packed fp32x2 helpers (Blackwell FFMA2) ----------------
__device__ __forceinline__ unsigned long long ffma2(unsigned long long a,
                                                    unsigned long long b,
                                                    unsigned long long c)
{
    unsigned long long d;
    asm("fma.rn.f32x2 %0, %1, %2, %3;" : "=l"(d) : "l"(a), "l"(b), "l"(c));
    return d;
}
__device__ __forceinline__ unsigned long long splat2(float x)
{
    unsigned long long d;
    unsigned int xi = __float_as_uint(x);
    asm("mov.b64 %0, {%1, %1};" : "=l"(d) : "r"(xi));
    return d;
}

// ---------------- A-operand gather (all float4-safe: every segment boundary %4==0) ----
// AK=0 plain [lda,aoff]; AK=1 TGN neighbor concat; AK=2 Q concat (emb|td or zeros);
// AK=3 FFN concat (attn 272 | emb 172)
template<int AK>
__device__ __forceinline__ float4 loadA4(const float* __restrict__ p0,
                                         const float* __restrict__ p1,
                                         const float* __restrict__ p2,
                                         int lda, int aoff, int row, int k4)
{
    if (AK == 0) {
        return *reinterpret_cast<const float4*>(p0 + (size_t)row*lda + aoff + k4);
    } else if (AK == 1) {
        int j = k4 / KDIM;
        int c = k4 - j*KDIM;
        int nb = row*NN + j;
        const float* p;
        if (c < DD)            p = p0 + (size_t)nb*DD   + c;
        else if (c < DD+EDGE_) p = p1 + (size_t)nb*EDGE_ + (c-DD);
        else                   p = p2 + (size_t)nb*TDIM + (c-DD-EDGE_);
        return *reinterpret_cast<const float4*>(p);
    } else if (AK == 2) {
        if (k4 < DD) return *reinterpret_cast<const float4*>(p0 + (size_t)row*DD + k4);
        if (p1)      return *reinterpret_cast<const float4*>(p1 + (size_t)row*TDIM + (k4-DD));
        return make_float4(0.f,0.f,0.f,0.f);
    } else { // AK == 3
        if (k4 < EE) return *reinterpret_cast<const float4*>(p0 + (size_t)row*EE + k4);
        return *reinterpret_cast<const float4*>(p1 + (size_t)row*DD + (k4-EE));
    }
}

// ---------------- generic NT SGEMM: C[m,n] = (sum_k A[m,k]*W[n,k] + bias[n])*scale ----
// BM=128 BN=64 BK=8, 256 threads, 8x4 per thread, FFMA2 inner loop.
template<int AK>
__global__ __launch_bounds__(256)
void gemm_k(const float* __restrict__ p0, const float* __restrict__ p1,
            const float* __restrict__ p2, int lda, int aoff,
            const float* __restrict__ W, int ldw, int woff,
            const float* __restrict__ bias,
            float* __restrict__ C, int ldc, int coff,
            int M, int N, int K, float scale, int relu)
{
    __shared__ __align__(16) float As[8][128];
    __shared__ __align__(16) float Ws[8][64];

    const int tid  = threadIdx.x;
    const int row0 = blockIdx.y * 128;
    const int n0   = blockIdx.x * 64;
    const int arow = tid >> 1, akq = tid & 1;
    const int wn   = tid >> 1, wkq = tid & 1;   // tid < 128 only
    const int tx   = tid & 15, ty = tid >> 4;

    // accumulators: 8 rows x 2 packed-f32x2 (covers 4 cols)
    unsigned long long acc[8][2];
    #pragma unroll
    for (int i = 0; i < 8; i++) { acc[i][0] = 0ull; acc[i][1] = 0ull; }

    for (int kt = 0; kt < K; kt += 8) {
        {
            int ka = kt + akq*4;
            float4 av = (ka < K) ? loadA4<AK>(p0,p1,p2,lda,aoff,row0+arow,ka)
                                 : make_float4(0.f,0.f,0.f,0.f);
            As[akq*4+0][arow] = av.x;
            As[akq*4+1][arow] = av.y;
            As[akq*4+2][arow] = av.z;
            As[akq*4+3][arow] = av.w;
        }
        if (tid < 128) {
            int kw = kt + wkq*4;
            int n  = n0 + wn;
            float4 wv = (kw < K && n < N)
                ? *reinterpret_cast<const float4*>(W + (size_t)n*ldw + woff + kw)
                : make_float4(0.f,0.f,0.f,0.f);
            Ws[wkq*4+0][wn] = wv.x;
            Ws[wkq*4+1][wn] = wv.y;
            Ws[wkq*4+2][wn] = wv.z;
            Ws[wkq*4+3][wn] = wv.w;
        }
        __syncthreads();
        #pragma unroll
        for (int kk = 0; kk < 8; kk++) {
            const unsigned long long* bw =
                reinterpret_cast<const unsigned long long*>(&Ws[kk][tx*4]);
            unsigned long long b0 = bw[0];
            unsigned long long b1 = bw[1];
            #pragma unroll
            for (int i = 0; i < 8; i++) {
                unsigned long long av = splat2(As[kk][ty*8+i]);
                acc[i][0] = ffma2(av, b0, acc[i][0]);
                acc[i][1] = ffma2(av, b1, acc[i][1]);
            }
        }
        __syncthreads();
    }

    #pragma unroll
    for (int i = 0; i < 8; i++) {
        int row = row0 + ty*8 + i;
        #pragma unroll
        for (int jp = 0; jp < 2; jp++) {
            float2 v2 = *reinterpret_cast<float2*>(&acc[i][jp]);
            float vv[2] = {v2.x, v2.y};
            #pragma unroll
            for (int u = 0; u < 2; u++) {
                int col = n0 + tx*4 + jp*2 + u;
                if (row < M && col < N) {
                    float v = vv[u];
                    if (bias) v += bias[col];
                    v *= scale;
                    if (relu) v = fmaxf(v, 0.f);
                    C[(size_t)row*ldc + coff + col] = v;
                }
            }
        }
    }
}

// ---------------- pack Wk|Wv and bk|bv into one operand ----------------
__global__ void pack_wkv_k(const float* __restrict__ Wk, const float* __restrict__ Wv,
                           const float* __restrict__ bk, const float* __restrict__ bv)
{
    int idx = blockIdx.x*256 + threadIdx.x;
    const int tot = NKV*KDT;
    if (idx < tot)
        g_Wkv[idx] = (idx < EE*KDT) ? Wk[idx] : Wv[idx - EE*KDT];
    if (idx < NKV)
        g_bkv[idx] = (idx < EE) ? bk[idx] : bv[idx - EE];
}

// ---------------- propagation-0 attention: per-source 10x10, H=2 ----------------
__global__ __launch_bounds__(256)
void attn0_k(const float* __restrict__ qp, const float* __restrict__ kvp,
             float* __restrict__ out)
{
    __shared__ float sq [NN*EE];    // 2720
    __shared__ float skv[NN*NKV];   // 5440
    __shared__ float sc[2][NN][NN];

    int s = blockIdx.x;
    int tid = threadIdx.x;
    size_t qb = (size_t)s*NN*EE;
    size_t kb = (size_t)s*NN*NKV;

    for (int i = tid; i < NN*EE;  i += 256) sq[i]  = qp[qb + i];
    for (int i = tid; i < NN*NKV; i += 256) skv[i] = kvp[kb + i];
    __syncthreads();

    if (tid < 2*NN*NN) {
        int h = tid / (NN*NN);
        int r = tid - h*NN*NN;
        int i = r / NN, j = r - i*NN;
        int off = h*HDIM;
        const float* q = sq  + i*EE  + off;
        const float* k = skv + j*NKV + off;
        float sum = 0.f;
        #pragma unroll 4
        for (int d = 0; d < HDIM; d++) sum = fmaf(q[d], k[d], sum);
        sc[h][i][j] = sum;
    }
    __syncthreads();

    if (tid < 2*NN) {
        int h = tid / NN, i = tid - h*NN;
        float m = -1e30f;
        #pragma unroll
        for (int j = 0; j < NN; j++) m = fmaxf(m, sc[h][i][j]);
        float ssum = 0.f;
        #pragma unroll
        for (int j = 0; j < NN; j++) {
            float e = expf(sc[h][i][j] - m);
            sc[h][i][j] = e;
            ssum += e;
        }
        float inv = 1.f / ssum;
        #pragma unroll
        for (int j = 0; j < NN; j++) sc[h][i][j] *= inv;
    }
    __syncthreads();

    for (int t = tid; t < NN*EE; t += 256) {
        int i = t / EE, col = t - i*EE;
        int h = (col >= HDIM) ? 1 : 0;
        float sum = 0.f;
        #pragma unroll
        for (int j = 0; j < NN; j++)
            sum = fmaf(sc[h][i][j], skv[j*NKV + EE + col], sum);
        out[qb + t] = sum;
    }
}

// ---------------- row softmax over 2048 (prop 1) ----------------
__global__ __launch_bounds__(256)
void softmax_k(float* __restrict__ p)
{
    __shared__ float red[8];
    size_t base = (size_t)blockIdx.x * 2048;
    int tid = threadIdx.x;

    float v[8];
    float m = -1e30f;
    #pragma unroll
    for (int u = 0; u < 8; u++) {
        v[u] = p[base + tid + u*256];
        m = fmaxf(m, v[u]);
    }
    #pragma unroll
    for (int o = 16; o; o >>= 1) m = fmaxf(m, __shfl_xor_sync(0xffffffffu, m, o));
    if ((tid & 31) == 0) red[tid >> 5] = m;
    __syncthreads();
    float mm = red[0];
    #pragma unroll
    for (int i = 1; i < 8; i++) mm = fmaxf(mm, red[i]);

    float s = 0.f;
    #pragma unroll
    for (int u = 0; u < 8; u++) {
        v[u] = __expf(v[u] - mm);
        s += v[u];
    }
    #pragma unroll
    for (int o = 16; o; o >>= 1) s += __shfl_xor_sync(0xffffffffu, s, o);
    __syncthreads();
    if ((tid & 31) == 0) red[tid >> 5] = s;
    __syncthreads();
    float tot = 0.f;
    #pragma unroll
    for (int i = 0; i < 8; i++) tot += red[i];
    float inv = 1.f / tot;
    #pragma unroll
    for (int u = 0; u < 8; u++) p[base + tid + u*256] = v[u] * inv;
}

// ---------------- transpose vp1 into [h*136+d][2048] for the PV GEMM ----------------
__global__ void transpose_v_k(const float* __restrict__ kvp, float* __restrict__ vT)
{
    int idx = blockIdx.x*256 + threadIdx.x;
    if (idx >= 2*HDIM*SZ) return;
    int j  = idx & 2047;
    int hd = idx >> 11;           // h*136 + d
    vT[idx] = kvp[(size_t)j*NKV + EE + hd];
}

// ---------------- launcher ----------------
extern "C" void kernel_launch(void* const* d_in, const int* in_sizes, int n_in,
                              void* d_out, int out_size)
{
    const float* emb0  = (const float*)d_in[0];
    const float* edge0 = (const float*)d_in[1];
    const float* td0   = (const float*)d_in[2];
    const float* emb1  = (const float*)d_in[3];
    const float* edge1 = (const float*)d_in[4];
    const float* td1   = (const float*)d_in[5];
    const float* emb2  = (const float*)d_in[6];
    const float* Wq = (const float*)d_in[7];
    const float* bq = (const float*)d_in[8];
    const float* Wk = (const float*)d_in[9];
    const float* bk = (const float*)d_in[10];
    const float* Wv = (const float*)d_in[11];
    const float* bv = (const float*)d_in[12];
    const float* Wo = (const float*)d_in[13];
    const float* bo = (const float*)d_in[14];
    const float* W1 = (const float*)d_in[15];
    const float* b1 = (const float*)d_in[16];
    const float* W2 = (const float*)d_in[17];
    const float* b2 = (const float*)d_in[18];
    float* out = (float*)d_out;

    float *qp0, *kvp0, *attn0, *a0, *h0;
    float *qp1, *kvp1, *scores, *vT, *attn1, *a1, *h1, *wkv, *bkv;
    cudaGetSymbolAddress((void**)&qp0,   g_qp0);
    cudaGetSymbolAddress((void**)&kvp0,  g_kvp0);
    cudaGetSymbolAddress((void**)&attn0, g_attn0);
    cudaGetSymbolAddress((void**)&a0,    g_a0);
    cudaGetSymbolAddress((void**)&h0,    g_h0);
    cudaGetSymbolAddress((void**)&qp1,   g_qp1);
    cudaGetSymbolAddress((void**)&kvp1,  g_kvp1);
    cudaGetSymbolAddress((void**)&scores,g_scores);
    cudaGetSymbolAddress((void**)&vT,    g_vT);
    cudaGetSymbolAddress((void**)&attn1, g_attn1);
    cudaGetSymbolAddress((void**)&a1,    g_a1);
    cudaGetSymbolAddress((void**)&h1,    g_h1);
    cudaGetSymbolAddress((void**)&wkv,   g_Wkv);
    cudaGetSymbolAddress((void**)&bkv,   g_bkv);

    const float SCALE = 0.08574929257125441f;  // 1/sqrt(136)

    pack_wkv_k<<<cdiv(NKV*KDT, 256), 256>>>(Wk, Wv, bk, bv);

    // ======== propagation 0 ========
    // qp0 = (concat(emb1,td1) @ Wq^T + bq) * scale            (20480 x 272)
    gemm_k<2><<<dim3(cdiv(EE,64), cdiv(M0,128)), 256>>>(
        emb1, td1, nullptr, 0, 0, Wq, EE, 0, bq, qp0, EE, 0, M0, EE, EE, SCALE, 0);
    // kvp0 = neigh0 @ [Wk|Wv]^T + [bk|bv]                     (20480 x 544)
    gemm_k<1><<<dim3(cdiv(NKV,64), cdiv(M0,128)), 256>>>(
        emb0, edge0, td0, 0, 0, wkv, KDT, 0, bkv, kvp0, NKV, 0, M0, NKV, KDT, 1.f, 0);
    // per-source 10x10 attention
    attn0_k<<<SZ, 256>>>(qp0, kvp0, attn0);
    // a0 = attn0 @ Wo^T + bo
    gemm_k<0><<<dim3(cdiv(EE,64), cdiv(M0,128)), 256>>>(
        attn0, nullptr, nullptr, EE, 0, Wo, EE, 0, bo, a0, EE, 0, M0, EE, EE, 1.f, 0);
    // h0 = relu(concat(a0,emb1) @ W1^T + b1)
    gemm_k<3><<<dim3(cdiv(DD,64), cdiv(M0,128)), 256>>>(
        a0, emb1, nullptr, 0, 0, W1, KDIM, 0, b1, h0, DD, 0, M0, DD, KDIM, 1.f, 1);
    // r0 = h0 @ W2^T + b2  -> out
    gemm_k<0><<<dim3(cdiv(DD,64), cdiv(M0,128)), 256>>>(
        h0, nullptr, nullptr, DD, 0, W2, DD, 0, b2, out + OUT_R0, DD, 0, M0, DD, DD, 1.f, 0);

    // ======== propagation 1 ========
    // qp1 = (concat(emb2, zeros) @ Wq^T + bq) * scale          (2048 x 272)
    gemm_k<2><<<dim3(cdiv(EE,64), cdiv(SZ,128)), 256>>>(
        emb2, nullptr, nullptr, 0, 0, Wq, EE, 0, bq, qp1, EE, 0, SZ, EE, EE, SCALE, 0);
    // kvp1 = neigh1 @ [Wk|Wv]^T + [bk|bv]                      (2048 x 544)
    gemm_k<1><<<dim3(cdiv(NKV,64), cdiv(SZ,128)), 256>>>(
        emb1, edge1, td1, 0, 0, wkv, KDT, 0, bkv, kvp1, NKV, 0, SZ, NKV, KDT, 1.f, 0);
    // scores[h] = qp1[:,h*136:] @ kp1[:,h*136:]^T              (2 x 2048 x 2048)
    for (int h = 0; h < 2; h++) {
        gemm_k<0><<<dim3(cdiv(SZ,64), cdiv(SZ,128)), 256>>>(
            qp1, nullptr, nullptr, EE, h*HDIM, kvp1, NKV, h*HDIM, nullptr,
            scores + (size_t)h*SZ*SZ, SZ, 0, SZ, SZ, HDIM, 1.f, 0);
    }
    softmax_k<<<2*SZ, 256>>>(scores);
    transpose_v_k<<<cdiv(2*HDIM*SZ, 256), 256>>>(kvp1, vT);
    // attn1[:, h*136:] = P[h] @ vp1[:, h*136:]
    for (int h = 0; h < 2; h++) {
        gemm_k<0><<<dim3(cdiv(HDIM,64), cdiv(SZ,128)), 256>>>(
            scores + (size_t)h*SZ*SZ, nullptr, nullptr, SZ, 0,
            vT + (size_t)h*HDIM*SZ, SZ, 0, nullptr,
            attn1, EE, h*HDIM, SZ, HDIM, SZ, 1.f, 0);
    }
    // a1 = attn1 @ Wo^T + bo
    gemm_k<0><<<dim3(cdiv(EE,64), cdiv(SZ,128)), 256>>>(
        attn1, nullptr, nullptr, EE, 0, Wo, EE, 0, bo, a1, EE, 0, SZ, EE, EE, 1.f, 0);
    // h1 = relu(concat(a1,emb2) @ W1^T + b1)
    gemm_k<3><<<dim3(cdiv(DD,64), cdiv(SZ,128)), 256>>>(
        a1, emb2, nullptr, 0, 0, W1, KDIM, 0, b1, h1, DD, 0, SZ, DD, KDIM, 1.f, 1);
    // r1 = h1 @ W2^T + b2 -> out
    gemm_k<0><<<dim3(cdiv(DD,64), cdiv(SZ,128)), 256>>>(
        h1, nullptr, nullptr, DD, 0, W2, DD, 0, b2, out + OUT_R1, DD, 0, SZ, DD, DD, 1.f, 0);

    // ======== pass-through outputs ========
    cudaMemcpyAsync(out + OUT_E1, edge1, (size_t)SZ*NN*EDGE_*sizeof(float),
                    cudaMemcpyDeviceToDevice);
    cudaMemcpyAsync(out + OUT_T1, td1, (size_t)SZ*NN*TDIM*sizeof(float),
                    cudaMemcpyDeviceToDevice);
}

// round 3
// speedup vs baseline: 1.6943x; 1.6067x over previous
#include <cuda_runtime.h>
#include <cuda_bf16.h>
#include <math.h>

// ---------------- problem constants ----------------
#define SZ    2048
#define NN    10
#define DD    172
#define EDGE_ 172
#define TDIM  100
#define EE    272      // D + TD
#define KDIM  444      // D + EDGE + TD
#define KDT   4440     // KDIM * N
#define HDIM  136
#define M0    (SZ*NN)  // 20480
#define NKV   544      // 272 kp | 272 vp

// output layout (floats)
#define OUT_R0 0
#define OUT_R1 3522560
#define OUT_E1 3874816
#define OUT_T1 7397376

// ---------------- scratch ----------------
__device__ float g_qp0 [M0*EE];
__device__ float g_kvp0[M0*NKV];
__device__ float g_attn0[M0*EE];
__device__ float g_a0  [M0*EE];
__device__ float g_h0  [M0*DD];
__device__ float g_qp1 [SZ*EE];
__device__ float g_kvp1[SZ*NKV];
__device__ float g_scores[2u*2048u*2048u];
__device__ float g_vT  [2*HDIM*SZ];
__device__ float g_attn1[SZ*EE];
__device__ float g_a1  [SZ*EE];
__device__ float g_h1  [SZ*DD];
__device__ float g_Wkv [NKV*KDT];
__device__ float g_bkv [NKV];

static inline int cdiv(int a, int b) { return (a + b - 1) / b; }

// ---------------- tf32 helpers ----------------
__device__ __forceinline__ unsigned int f2tf32(float x)
{
    unsigned int r;
    asm("cvt.rna.tf32.f32 %0, %1;" : "=r"(r) : "f"(x));
    return r;
}

__device__ __forceinline__ void mma_tf32(float* c,
                                         unsigned int a0, unsigned int a1,
                                         unsigned int a2, unsigned int a3,
                                         unsigned int b0, unsigned int b1)
{
    asm volatile(
        "mma.sync.aligned.m16n8k8.row.col.f32.tf32.tf32.f32 "
        "{%0,%1,%2,%3}, {%4,%5,%6,%7}, {%8,%9}, {%0,%1,%2,%3};"
        : "+f"(c[0]), "+f"(c[1]), "+f"(c[2]), "+f"(c[3])
        : "r"(a0), "r"(a1), "r"(a2), "r"(a3), "r"(b0), "r"(b1));
}

// ---------------- A-operand gather (float4-safe: all segment boundaries %4==0) ----
// AK=0 plain; AK=1 TGN neighbor concat; AK=2 Q concat (emb|td or zeros);
// AK=3 FFN concat (272 | 172)
template<int AK>
__device__ __forceinline__ float4 loadA4(const float* __restrict__ p0,
                                         const float* __restrict__ p1,
                                         const float* __restrict__ p2,
                                         int lda, int aoff, int row, int k4)
{
    if (AK == 0) {
        return *reinterpret_cast<const float4*>(p0 + (size_t)row*lda + aoff + k4);
    } else if (AK == 1) {
        int j = k4 / KDIM;
        int c = k4 - j*KDIM;
        int nb = row*NN + j;
        const float* p;
        if (c < DD)            p = p0 + (size_t)nb*DD   + c;
        else if (c < DD+EDGE_) p = p1 + (size_t)nb*EDGE_ + (c-DD);
        else                   p = p2 + (size_t)nb*TDIM + (c-DD-EDGE_);
        return *reinterpret_cast<const float4*>(p);
    } else if (AK == 2) {
        if (k4 < DD) return *reinterpret_cast<const float4*>(p0 + (size_t)row*DD + k4);
        if (p1)      return *reinterpret_cast<const float4*>(p1 + (size_t)row*TDIM + (k4-DD));
        return make_float4(0.f,0.f,0.f,0.f);
    } else {
        if (k4 < EE) return *reinterpret_cast<const float4*>(p0 + (size_t)row*EE + k4);
        return *reinterpret_cast<const float4*>(p1 + (size_t)row*DD + (k4-EE));
    }
}

// ---------------- tf32 tensor-core NT GEMM ----------------
// C[m,n] = (sum_k A[m,k]*W[n,k] + bias[n]) * scale  [+relu]
// BM=128 BN=64 BK=16, 256 threads = 8 warps (2m x 4n), warp tile 64x16.
// Requires M % 128 == 0 (true for all call sites), K % 4 == 0.
template<int AK>
__global__ __launch_bounds__(256)
void tgemm_k(const float* __restrict__ p0, const float* __restrict__ p1,
             const float* __restrict__ p2, int lda, int aoff,
             const float* __restrict__ W, int ldw, int woff,
             const float* __restrict__ bias,
             float* __restrict__ C, int ldc, int coff,
             int M, int N, int K, float scale, int relu)
{
    __shared__ __align__(16) unsigned int As[128][20];  // tf32 bits, pad->conflict-free
    __shared__ __align__(16) unsigned int Ws[64][20];

    const int tid  = threadIdx.x;
    const int lane = tid & 31;
    const int warp = tid >> 5;
    const int wm   = (warp & 1) * 64;
    const int wn   = (warp >> 1) * 16;
    const int grp  = lane >> 2;
    const int qid  = lane & 3;
    const int row0 = blockIdx.y * 128;
    const int n0   = blockIdx.x * 64;

    float acc[4][2][4];
    #pragma unroll
    for (int mf = 0; mf < 4; mf++)
        #pragma unroll
        for (int nf = 0; nf < 2; nf++)
            #pragma unroll
            for (int u = 0; u < 4; u++) acc[mf][nf][u] = 0.f;

    for (int kt = 0; kt < K; kt += 16) {
        // stage A: 128 rows x 16 k = 512 float4 slots
        #pragma unroll
        for (int i = 0; i < 2; i++) {
            int idx = tid + i*256;
            int r   = idx >> 2;
            int kq  = idx & 3;
            int ka  = kt + kq*4;
            float4 v = (ka < K) ? loadA4<AK>(p0,p1,p2,lda,aoff,row0+r,ka)
                                : make_float4(0.f,0.f,0.f,0.f);
            uint4 t;
            t.x = f2tf32(v.x); t.y = f2tf32(v.y);
            t.z = f2tf32(v.z); t.w = f2tf32(v.w);
            *reinterpret_cast<uint4*>(&As[r][kq*4]) = t;
        }
        // stage W: 64 rows x 16 k = 256 float4 slots
        {
            int r  = tid >> 2;
            int kq = tid & 3;
            int kw = kt + kq*4;
            int n  = n0 + r;
            float4 v = (kw < K && n < N)
                ? *reinterpret_cast<const float4*>(W + (size_t)n*ldw + woff + kw)
                : make_float4(0.f,0.f,0.f,0.f);
            uint4 t;
            t.x = f2tf32(v.x); t.y = f2tf32(v.y);
            t.z = f2tf32(v.z); t.w = f2tf32(v.w);
            *reinterpret_cast<uint4*>(&Ws[r][kq*4]) = t;
        }
        __syncthreads();

        #pragma unroll
        for (int kf = 0; kf < 2; kf++) {
            unsigned int b[2][2];
            #pragma unroll
            for (int nf = 0; nf < 2; nf++) {
                int nl = wn + nf*8 + grp;
                b[nf][0] = Ws[nl][kf*8 + qid];
                b[nf][1] = Ws[nl][kf*8 + 4 + qid];
            }
            #pragma unroll
            for (int mf = 0; mf < 4; mf++) {
                int r = wm + mf*16 + grp;
                unsigned int a0 = As[r    ][kf*8 + qid];
                unsigned int a1 = As[r + 8][kf*8 + qid];
                unsigned int a2 = As[r    ][kf*8 + 4 + qid];
                unsigned int a3 = As[r + 8][kf*8 + 4 + qid];
                #pragma unroll
                for (int nf = 0; nf < 2; nf++)
                    mma_tf32(acc[mf][nf], a0, a1, a2, a3, b[nf][0], b[nf][1]);
            }
        }
        __syncthreads();
    }

    // epilogue: c0,c1 -> (row, col),(row, col+1); c2,c3 -> (row+8, ...)
    #pragma unroll
    for (int mf = 0; mf < 4; mf++) {
        #pragma unroll
        for (int nf = 0; nf < 2; nf++) {
            int col = n0 + wn + nf*8 + 2*qid;
            if (col >= N) continue;
            float bsum0 = bias ? bias[col]   : 0.f;
            float bsum1 = bias ? bias[col+1] : 0.f;
            #pragma unroll
            for (int half = 0; half < 2; half++) {
                int row = row0 + wm + mf*16 + grp + half*8;
                if (row >= M) continue;
                float v0 = (acc[mf][nf][half*2+0] + bsum0) * scale;
                float v1 = (acc[mf][nf][half*2+1] + bsum1) * scale;
                if (relu) { v0 = fmaxf(v0, 0.f); v1 = fmaxf(v1, 0.f); }
                float2 o = make_float2(v0, v1);
                *reinterpret_cast<float2*>(C + (size_t)row*ldc + coff + col) = o;
            }
        }
    }
}

// ---------------- pack Wk|Wv and bk|bv ----------------
__global__ void pack_wkv_k(const float* __restrict__ Wk, const float* __restrict__ Wv,
                           const float* __restrict__ bk, const float* __restrict__ bv)
{
    int idx = blockIdx.x*256 + threadIdx.x;
    const int tot = NKV*KDT;
    if (idx < tot)
        g_Wkv[idx] = (idx < EE*KDT) ? Wk[idx] : Wv[idx - EE*KDT];
    if (idx < NKV)
        g_bkv[idx] = (idx < EE) ? bk[idx] : bv[idx - EE];
}

// ---------------- propagation-0 attention: per-source 10x10, H=2 ----------------
__global__ __launch_bounds__(256)
void attn0_k(const float* __restrict__ qp, const float* __restrict__ kvp,
             float* __restrict__ out)
{
    __shared__ float sq [NN*EE];
    __shared__ float skv[NN*NKV];
    __shared__ float sc[2][NN][NN];

    int s = blockIdx.x;
    int tid = threadIdx.x;
    size_t qb = (size_t)s*NN*EE;
    size_t kb = (size_t)s*NN*NKV;

    for (int i = tid; i < NN*EE;  i += 256) sq[i]  = qp[qb + i];
    for (int i = tid; i < NN*NKV; i += 256) skv[i] = kvp[kb + i];
    __syncthreads();

    if (tid < 2*NN*NN) {
        int h = tid / (NN*NN);
        int r = tid - h*NN*NN;
        int i = r / NN, j = r - i*NN;
        int off = h*HDIM;
        const float* q = sq  + i*EE  + off;
        const float* k = skv + j*NKV + off;
        float sum = 0.f;
        #pragma unroll 4
        for (int d = 0; d < HDIM; d++) sum = fmaf(q[d], k[d], sum);
        sc[h][i][j] = sum;
    }
    __syncthreads();

    if (tid < 2*NN) {
        int h = tid / NN, i = tid - h*NN;
        float m = -1e30f;
        #pragma unroll
        for (int j = 0; j < NN; j++) m = fmaxf(m, sc[h][i][j]);
        float ssum = 0.f;
        #pragma unroll
        for (int j = 0; j < NN; j++) {
            float e = expf(sc[h][i][j] - m);
            sc[h][i][j] = e;
            ssum += e;
        }
        float inv = 1.f / ssum;
        #pragma unroll
        for (int j = 0; j < NN; j++) sc[h][i][j] *= inv;
    }
    __syncthreads();

    for (int t = tid; t < NN*EE; t += 256) {
        int i = t / EE, col = t - i*EE;
        int h = (col >= HDIM) ? 1 : 0;
        float sum = 0.f;
        #pragma unroll
        for (int j = 0; j < NN; j++)
            sum = fmaf(sc[h][i][j], skv[j*NKV + EE + col], sum);
        out[qb + t] = sum;
    }
}

// ---------------- row softmax over 2048 (prop 1) ----------------
__global__ __launch_bounds__(256)
void softmax_k(float* __restrict__ p)
{
    __shared__ float red[8];
    size_t base = (size_t)blockIdx.x * 2048;
    int tid = threadIdx.x;

    float v[8];
    float m = -1e30f;
    #pragma unroll
    for (int u = 0; u < 8; u++) {
        v[u] = p[base + tid + u*256];
        m = fmaxf(m, v[u]);
    }
    #pragma unroll
    for (int o = 16; o; o >>= 1) m = fmaxf(m, __shfl_xor_sync(0xffffffffu, m, o));
    if ((tid & 31) == 0) red[tid >> 5] = m;
    __syncthreads();
    float mm = red[0];
    #pragma unroll
    for (int i = 1; i < 8; i++) mm = fmaxf(mm, red[i]);

    float s = 0.f;
    #pragma unroll
    for (int u = 0; u < 8; u++) {
        v[u] = __expf(v[u] - mm);
        s += v[u];
    }
    #pragma unroll
    for (int o = 16; o; o >>= 1) s += __shfl_xor_sync(0xffffffffu, s, o);
    __syncthreads();
    if ((tid & 31) == 0) red[tid >> 5] = s;
    __syncthreads();
    float tot = 0.f;
    #pragma unroll
    for (int i = 0; i < 8; i++) tot += red[i];
    float inv = 1.f / tot;
    #pragma unroll
    for (int u = 0; u < 8; u++) p[base + tid + u*256] = v[u] * inv;
}

// ---------------- transpose vp1 into [h*136+d][2048] ----------------
__global__ void transpose_v_k(const float* __restrict__ kvp, float* __restrict__ vT)
{
    int idx = blockIdx.x*256 + threadIdx.x;
    if (idx >= 2*HDIM*SZ) return;
    int j  = idx & 2047;
    int hd = idx >> 11;
    vT[idx] = kvp[(size_t)j*NKV + EE + hd];
}

// ---------------- launcher ----------------
extern "C" void kernel_launch(void* const* d_in, const int* in_sizes, int n_in,
                              void* d_out, int out_size)
{
    const float* emb0  = (const float*)d_in[0];
    const float* edge0 = (const float*)d_in[1];
    const float* td0   = (const float*)d_in[2];
    const float* emb1  = (const float*)d_in[3];
    const float* edge1 = (const float*)d_in[4];
    const float* td1   = (const float*)d_in[5];
    const float* emb2  = (const float*)d_in[6];
    const float* Wq = (const float*)d_in[7];
    const float* bq = (const float*)d_in[8];
    const float* Wk = (const float*)d_in[9];
    const float* bk = (const float*)d_in[10];
    const float* Wv = (const float*)d_in[11];
    const float* bv = (const float*)d_in[12];
    const float* Wo = (const float*)d_in[13];
    const float* bo = (const float*)d_in[14];
    const float* W1 = (const float*)d_in[15];
    const float* b1 = (const float*)d_in[16];
    const float* W2 = (const float*)d_in[17];
    const float* b2 = (const float*)d_in[18];
    float* out = (float*)d_out;

    float *qp0, *kvp0, *attn0, *a0, *h0;
    float *qp1, *kvp1, *scores, *vT, *attn1, *a1, *h1, *wkv, *bkv;
    cudaGetSymbolAddress((void**)&qp0,   g_qp0);
    cudaGetSymbolAddress((void**)&kvp0,  g_kvp0);
    cudaGetSymbolAddress((void**)&attn0, g_attn0);
    cudaGetSymbolAddress((void**)&a0,    g_a0);
    cudaGetSymbolAddress((void**)&h0,    g_h0);
    cudaGetSymbolAddress((void**)&qp1,   g_qp1);
    cudaGetSymbolAddress((void**)&kvp1,  g_kvp1);
    cudaGetSymbolAddress((void**)&scores,g_scores);
    cudaGetSymbolAddress((void**)&vT,    g_vT);
    cudaGetSymbolAddress((void**)&attn1, g_attn1);
    cudaGetSymbolAddress((void**)&a1,    g_a1);
    cudaGetSymbolAddress((void**)&h1,    g_h1);
    cudaGetSymbolAddress((void**)&wkv,   g_Wkv);
    cudaGetSymbolAddress((void**)&bkv,   g_bkv);

    const float SCALE = 0.08574929257125441f;  // 1/sqrt(136)

    pack_wkv_k<<<cdiv(NKV*KDT, 256), 256>>>(Wk, Wv, bk, bv);

    // ======== propagation 0 ========
    tgemm_k<2><<<dim3(cdiv(EE,64), cdiv(M0,128)), 256>>>(
        emb1, td1, nullptr, 0, 0, Wq, EE, 0, bq, qp0, EE, 0, M0, EE, EE, SCALE, 0);
    tgemm_k<1><<<dim3(cdiv(NKV,64), cdiv(M0,128)), 256>>>(
        emb0, edge0, td0, 0, 0, wkv, KDT, 0, bkv, kvp0, NKV, 0, M0, NKV, KDT, 1.f, 0);
    attn0_k<<<SZ, 256>>>(qp0, kvp0, attn0);
    tgemm_k<0><<<dim3(cdiv(EE,64), cdiv(M0,128)), 256>>>(
        attn0, nullptr, nullptr, EE, 0, Wo, EE, 0, bo, a0, EE, 0, M0, EE, EE, 1.f, 0);
    tgemm_k<3><<<dim3(cdiv(DD,64), cdiv(M0,128)), 256>>>(
        a0, emb1, nullptr, 0, 0, W1, KDIM, 0, b1, h0, DD, 0, M0, DD, KDIM, 1.f, 1);
    tgemm_k<0><<<dim3(cdiv(DD,64), cdiv(M0,128)), 256>>>(
        h0, nullptr, nullptr, DD, 0, W2, DD, 0, b2, out + OUT_R0, DD, 0, M0, DD, DD, 1.f, 0);

    // ======== propagation 1 ========
    tgemm_k<2><<<dim3(cdiv(EE,64), cdiv(SZ,128)), 256>>>(
        emb2, nullptr, nullptr, 0, 0, Wq, EE, 0, bq, qp1, EE, 0, SZ, EE, EE, SCALE, 0);
    tgemm_k<1><<<dim3(cdiv(NKV,64), cdiv(SZ,128)), 256>>>(
        emb1, edge1, td1, 0, 0, wkv, KDT, 0, bkv, kvp1, NKV, 0, SZ, NKV, KDT, 1.f, 0);
    for (int h = 0; h < 2; h++) {
        tgemm_k<0><<<dim3(cdiv(SZ,64), cdiv(SZ,128)), 256>>>(
            qp1, nullptr, nullptr, EE, h*HDIM, kvp1, NKV, h*HDIM, nullptr,
            scores + (size_t)h*SZ*SZ, SZ, 0, SZ, SZ, HDIM, 1.f, 0);
    }
    softmax_k<<<2*SZ, 256>>>(scores);
    transpose_v_k<<<cdiv(2*HDIM*SZ, 256), 256>>>(kvp1, vT);
    for (int h = 0; h < 2; h++) {
        tgemm_k<0><<<dim3(cdiv(HDIM,64), cdiv(SZ,128)), 256>>>(
            scores + (size_t)h*SZ*SZ, nullptr, nullptr, SZ, 0,
            vT + (size_t)h*HDIM*SZ, SZ, 0, nullptr,
            attn1, EE, h*HDIM, SZ, HDIM, SZ, 1.f, 0);
    }
    tgemm_k<0><<<dim3(cdiv(EE,64), cdiv(SZ,128)), 256>>>(
        attn1, nullptr, nullptr, EE, 0, Wo, EE, 0, bo, a1, EE, 0, SZ, EE, EE, 1.f, 0);
    tgemm_k<3><<<dim3(cdiv(DD,64), cdiv(SZ,128)), 256>>>(
        a1, emb2, nullptr, 0, 0, W1, KDIM, 0, b1, h1, DD, 0, SZ, DD, KDIM, 1.f, 1);
    tgemm_k<0><<<dim3(cdiv(DD,64), cdiv(SZ,128)), 256>>>(
        h1, nullptr, nullptr, DD, 0, W2, DD, 0, b2, out + OUT_R1, DD, 0, SZ, DD, DD, 1.f, 0);

    // ======== pass-through outputs ========
    cudaMemcpyAsync(out + OUT_E1, edge1, (size_t)SZ*NN*EDGE_*sizeof(float),
                    cudaMemcpyDeviceToDevice);
    cudaMemcpyAsync(out + OUT_T1, td1, (size_t)SZ*NN*TDIM*sizeof(float),
                    cudaMemcpyDeviceToDevice);
}

// round 4
// speedup vs baseline: 2.4634x; 1.4539x over previous
#include <cuda_runtime.h>
#include <cuda_bf16.h>
#include <math.h>

// ---------------- problem constants ----------------
#define SZ    2048
#define NN    10
#define DD    172
#define EDGE_ 172
#define TDIM  100
#define EE    272      // D + TD
#define KDIM  444      // D + EDGE + TD
#define KDT   4440     // KDIM * N
#define HDIM  136
#define M0    (SZ*NN)  // 20480
#define NKV   544      // 272 kp | 272 vp

// output layout (floats)
#define OUT_R0 0
#define OUT_R1 3522560
#define OUT_E1 3874816
#define OUT_T1 7397376

// ---------------- scratch ----------------
__device__ float g_qp0 [M0*EE];
__device__ float g_kvp0[M0*NKV];
__device__ float g_attn0[M0*EE];
__device__ float g_a0  [M0*EE];
__device__ float g_h0  [M0*DD];
__device__ float g_qp1 [SZ*EE];
__device__ float g_kvp1[SZ*NKV];
__device__ float g_scores[2u*2048u*2048u];
__device__ float g_vT  [2*HDIM*SZ];
__device__ float g_attn1[SZ*EE];
__device__ float g_a1  [SZ*EE];
__device__ float g_h1  [SZ*DD];
__device__ float g_Wkv [NKV*KDT];
__device__ float g_bkv [NKV];

static inline int cdiv(int a, int b) { return (a + b - 1) / b; }

// ---------------- tf32 helpers ----------------
__device__ __forceinline__ unsigned int f2tf32(float x)
{
    unsigned int r;
    asm("cvt.rna.tf32.f32 %0, %1;" : "=r"(r) : "f"(x));
    return r;
}

__device__ __forceinline__ void mma_tf32(float* c,
                                         unsigned int a0, unsigned int a1,
                                         unsigned int a2, unsigned int a3,
                                         unsigned int b0, unsigned int b1)
{
    asm volatile(
        "mma.sync.aligned.m16n8k8.row.col.f32.tf32.tf32.f32 "
        "{%0,%1,%2,%3}, {%4,%5,%6,%7}, {%8,%9}, {%0,%1,%2,%3};"
        : "+f"(c[0]), "+f"(c[1]), "+f"(c[2]), "+f"(c[3])
        : "r"(a0), "r"(a1), "r"(a2), "r"(a3), "r"(b0), "r"(b1));
}

// ---------------- A-operand gather (float4-safe: all segment boundaries %4==0) ----
// AK=0 plain; AK=1 TGN neighbor concat; AK=2 Q concat (emb|td or zeros);
// AK=3 FFN concat (272 | 172)
template<int AK>
__device__ __forceinline__ float4 loadA4(const float* __restrict__ p0,
                                         const float* __restrict__ p1,
                                         const float* __restrict__ p2,
                                         int lda, int aoff, int row, int k4)
{
    if (AK == 0) {
        return *reinterpret_cast<const float4*>(p0 + (size_t)row*lda + aoff + k4);
    } else if (AK == 1) {
        int j = k4 / KDIM;
        int c = k4 - j*KDIM;
        int nb = row*NN + j;
        const float* p;
        if (c < DD)            p = p0 + (size_t)nb*DD   + c;
        else if (c < DD+EDGE_) p = p1 + (size_t)nb*EDGE_ + (c-DD);
        else                   p = p2 + (size_t)nb*TDIM + (c-DD-EDGE_);
        return *reinterpret_cast<const float4*>(p);
    } else if (AK == 2) {
        if (k4 < DD) return *reinterpret_cast<const float4*>(p0 + (size_t)row*DD + k4);
        if (p1)      return *reinterpret_cast<const float4*>(p1 + (size_t)row*TDIM + (k4-DD));
        return make_float4(0.f,0.f,0.f,0.f);
    } else {
        if (k4 < EE) return *reinterpret_cast<const float4*>(p0 + (size_t)row*EE + k4);
        return *reinterpret_cast<const float4*>(p1 + (size_t)row*DD + (k4-EE));
    }
}

// ================= WIDE tf32 GEMM: BM=128 BN=128 BK=16, double-buffered =======
// 256 threads = 8 warps (2m x 2n), warp tile 64x32.
// Requires M % 128 == 0. Used for the large-N GEMMs (kvp, scores).
template<int AK>
__global__ __launch_bounds__(256)
void tgemm_wide(const float* __restrict__ p0, const float* __restrict__ p1,
                const float* __restrict__ p2, int lda, int aoff,
                const float* __restrict__ W, int ldw, int woff,
                const float* __restrict__ bias,
                float* __restrict__ C, int ldc, int coff,
                int M, int N, int K, float scale)
{
    __shared__ __align__(16) unsigned int As[2][128][20];
    __shared__ __align__(16) unsigned int Ws[2][128][20];

    const int tid  = threadIdx.x;
    const int lane = tid & 31;
    const int warp = tid >> 5;
    const int wm   = (warp & 1) * 64;
    const int wn   = (warp >> 1 & 1) * 32 + (warp >> 2) * 64;  // 4 n-positions? no:
    // 8 warps = 2m x 4n?? -> we want 2m x 2n covering 128x128 with 64x32?? That is
    // 2*2=4 warps only. Use 2m x 4n with warp tile 64x32: wn = (warp>>1)*32.
    const int wn4  = (warp >> 1) * 32;
    const int grp  = lane >> 2;
    const int qid  = lane & 3;
    const int row0 = blockIdx.y * 128;
    const int n0   = blockIdx.x * 128;

    float acc[4][4][4];
    #pragma unroll
    for (int mf = 0; mf < 4; mf++)
        #pragma unroll
        for (int nf = 0; nf < 4; nf++)
            #pragma unroll
            for (int u = 0; u < 4; u++) acc[mf][nf][u] = 0.f;

    // staging registers
    float4 avr[2], wvr[2];

    const int r_a  = tid >> 2;         // 0..63  (x2 for 128 rows)
    const int kq_a = tid & 3;

    // ---- prologue: load tile 0 ----
    #pragma unroll
    for (int i = 0; i < 2; i++) {
        int r  = r_a + i*64;
        int ka = kq_a*4;
        avr[i] = (ka < K) ? loadA4<AK>(p0,p1,p2,lda,aoff,row0+r,ka)
                          : make_float4(0.f,0.f,0.f,0.f);
        int n  = n0 + r;
        wvr[i] = (ka < K && n < N)
            ? *reinterpret_cast<const float4*>(W + (size_t)n*ldw + woff + ka)
            : make_float4(0.f,0.f,0.f,0.f);
    }
    #pragma unroll
    for (int i = 0; i < 2; i++) {
        int r = r_a + i*64;
        uint4 t;
        t.x = f2tf32(avr[i].x); t.y = f2tf32(avr[i].y);
        t.z = f2tf32(avr[i].z); t.w = f2tf32(avr[i].w);
        *reinterpret_cast<uint4*>(&As[0][r][kq_a*4]) = t;
        t.x = f2tf32(wvr[i].x); t.y = f2tf32(wvr[i].y);
        t.z = f2tf32(wvr[i].z); t.w = f2tf32(wvr[i].w);
        *reinterpret_cast<uint4*>(&Ws[0][r][kq_a*4]) = t;
    }
    __syncthreads();

    int buf = 0;
    for (int kt = 0; kt < K; kt += 16) {
        const bool more = (kt + 16) < K;
        // issue next-tile global loads early
        if (more) {
            #pragma unroll
            for (int i = 0; i < 2; i++) {
                int r  = r_a + i*64;
                int ka = kt + 16 + kq_a*4;
                avr[i] = (ka < K) ? loadA4<AK>(p0,p1,p2,lda,aoff,row0+r,ka)
                                  : make_float4(0.f,0.f,0.f,0.f);
                int n  = n0 + r;
                wvr[i] = (ka < K && n < N)
                    ? *reinterpret_cast<const float4*>(W + (size_t)n*ldw + woff + ka)
                    : make_float4(0.f,0.f,0.f,0.f);
            }
        }

        // compute on current buffer
        #pragma unroll
        for (int kf = 0; kf < 2; kf++) {
            unsigned int b[4][2];
            #pragma unroll
            for (int nf = 0; nf < 4; nf++) {
                int nl = wn4 + nf*8 + grp;
                b[nf][0] = Ws[buf][nl][kf*8 + qid];
                b[nf][1] = Ws[buf][nl][kf*8 + 4 + qid];
            }
            #pragma unroll
            for (int mf = 0; mf < 4; mf++) {
                int r = wm + mf*16 + grp;
                unsigned int a0 = As[buf][r    ][kf*8 + qid];
                unsigned int a1 = As[buf][r + 8][kf*8 + qid];
                unsigned int a2 = As[buf][r    ][kf*8 + 4 + qid];
                unsigned int a3 = As[buf][r + 8][kf*8 + 4 + qid];
                #pragma unroll
                for (int nf = 0; nf < 4; nf++)
                    mma_tf32(acc[mf][nf], a0, a1, a2, a3, b[nf][0], b[nf][1]);
            }
        }

        // store next tile into alternate buffer
        if (more) {
            int nb = buf ^ 1;
            #pragma unroll
            for (int i = 0; i < 2; i++) {
                int r = r_a + i*64;
                uint4 t;
                t.x = f2tf32(avr[i].x); t.y = f2tf32(avr[i].y);
                t.z = f2tf32(avr[i].z); t.w = f2tf32(avr[i].w);
                *reinterpret_cast<uint4*>(&As[nb][r][kq_a*4]) = t;
                t.x = f2tf32(wvr[i].x); t.y = f2tf32(wvr[i].y);
                t.z = f2tf32(wvr[i].z); t.w = f2tf32(wvr[i].w);
                *reinterpret_cast<uint4*>(&Ws[nb][r][kq_a*4]) = t;
            }
        }
        __syncthreads();
        buf ^= 1;
    }

    // epilogue
    #pragma unroll
    for (int mf = 0; mf < 4; mf++) {
        #pragma unroll
        for (int nf = 0; nf < 4; nf++) {
            int col = n0 + wn4 + nf*8 + 2*qid;
            if (col >= N) continue;
            float bsum0 = bias ? bias[col]   : 0.f;
            float bsum1 = bias ? bias[col+1] : 0.f;
            #pragma unroll
            for (int half = 0; half < 2; half++) {
                int row = row0 + wm + mf*16 + grp + half*8;
                if (row >= M) continue;
                float v0 = (acc[mf][nf][half*2+0] + bsum0) * scale;
                float v1 = (acc[mf][nf][half*2+1] + bsum1) * scale;
                float2 o = make_float2(v0, v1);
                *reinterpret_cast<float2*>(C + (size_t)row*ldc + coff + col) = o;
            }
        }
    }
}

// ================= NARROW tf32 GEMM: BM=128 BN=64 BK=16 (round-3 proven) ======
template<int AK>
__global__ __launch_bounds__(256)
void tgemm_k(const float* __restrict__ p0, const float* __restrict__ p1,
             const float* __restrict__ p2, int lda, int aoff,
             const float* __restrict__ W, int ldw, int woff,
             const float* __restrict__ bias,
             float* __restrict__ C, int ldc, int coff,
             int M, int N, int K, float scale, int relu)
{
    __shared__ __align__(16) unsigned int As[128][20];
    __shared__ __align__(16) unsigned int Ws[64][20];

    const int tid  = threadIdx.x;
    const int lane = tid & 31;
    const int warp = tid >> 5;
    const int wm   = (warp & 1) * 64;
    const int wn   = (warp >> 1) * 16;
    const int grp  = lane >> 2;
    const int qid  = lane & 3;
    const int row0 = blockIdx.y * 128;
    const int n0   = blockIdx.x * 64;

    float acc[4][2][4];
    #pragma unroll
    for (int mf = 0; mf < 4; mf++)
        #pragma unroll
        for (int nf = 0; nf < 2; nf++)
            #pragma unroll
            for (int u = 0; u < 4; u++) acc[mf][nf][u] = 0.f;

    for (int kt = 0; kt < K; kt += 16) {
        #pragma unroll
        for (int i = 0; i < 2; i++) {
            int idx = tid + i*256;
            int r   = idx >> 2;
            int kq  = idx & 3;
            int ka  = kt + kq*4;
            float4 v = (ka < K) ? loadA4<AK>(p0,p1,p2,lda,aoff,row0+r,ka)
                                : make_float4(0.f,0.f,0.f,0.f);
            uint4 t;
            t.x = f2tf32(v.x); t.y = f2tf32(v.y);
            t.z = f2tf32(v.z); t.w = f2tf32(v.w);
            *reinterpret_cast<uint4*>(&As[r][kq*4]) = t;
        }
        {
            int r  = tid >> 2;
            int kq = tid & 3;
            int kw = kt + kq*4;
            int n  = n0 + r;
            float4 v = (kw < K && n < N)
                ? *reinterpret_cast<const float4*>(W + (size_t)n*ldw + woff + kw)
                : make_float4(0.f,0.f,0.f,0.f);
            uint4 t;
            t.x = f2tf32(v.x); t.y = f2tf32(v.y);
            t.z = f2tf32(v.z); t.w = f2tf32(v.w);
            *reinterpret_cast<uint4*>(&Ws[r][kq*4]) = t;
        }
        __syncthreads();

        #pragma unroll
        for (int kf = 0; kf < 2; kf++) {
            unsigned int b[2][2];
            #pragma unroll
            for (int nf = 0; nf < 2; nf++) {
                int nl = wn + nf*8 + grp;
                b[nf][0] = Ws[nl][kf*8 + qid];
                b[nf][1] = Ws[nl][kf*8 + 4 + qid];
            }
            #pragma unroll
            for (int mf = 0; mf < 4; mf++) {
                int r = wm + mf*16 + grp;
                unsigned int a0 = As[r    ][kf*8 + qid];
                unsigned int a1 = As[r + 8][kf*8 + qid];
                unsigned int a2 = As[r    ][kf*8 + 4 + qid];
                unsigned int a3 = As[r + 8][kf*8 + 4 + qid];
                #pragma unroll
                for (int nf = 0; nf < 2; nf++)
                    mma_tf32(acc[mf][nf], a0, a1, a2, a3, b[nf][0], b[nf][1]);
            }
        }
        __syncthreads();
    }

    #pragma unroll
    for (int mf = 0; mf < 4; mf++) {
        #pragma unroll
        for (int nf = 0; nf < 2; nf++) {
            int col = n0 + wn + nf*8 + 2*qid;
            if (col >= N) continue;
            float bsum0 = bias ? bias[col]   : 0.f;
            float bsum1 = bias ? bias[col+1] : 0.f;
            #pragma unroll
            for (int half = 0; half < 2; half++) {
                int row = row0 + wm + mf*16 + grp + half*8;
                if (row >= M) continue;
                float v0 = (acc[mf][nf][half*2+0] + bsum0) * scale;
                float v1 = (acc[mf][nf][half*2+1] + bsum1) * scale;
                if (relu) { v0 = fmaxf(v0, 0.f); v1 = fmaxf(v1, 0.f); }
                float2 o = make_float2(v0, v1);
                *reinterpret_cast<float2*>(C + (size_t)row*ldc + coff + col) = o;
            }
        }
    }
}

// ---------------- pack Wk|Wv and bk|bv ----------------
__global__ void pack_wkv_k(const float* __restrict__ Wk, const float* __restrict__ Wv,
                           const float* __restrict__ bk, const float* __restrict__ bv)
{
    int idx = blockIdx.x*256 + threadIdx.x;
    const int tot = NKV*KDT;
    if (idx < tot)
        g_Wkv[idx] = (idx < EE*KDT) ? Wk[idx] : Wv[idx - EE*KDT];
    if (idx < NKV)
        g_bkv[idx] = (idx < EE) ? bk[idx] : bv[idx - EE];
}

// ---------------- propagation-0 attention: per-source 10x10, H=2 ----------------
__global__ __launch_bounds__(256)
void attn0_k(const float* __restrict__ qp, const float* __restrict__ kvp,
             float* __restrict__ out)
{
    __shared__ float sq [NN*EE];
    __shared__ float skv[NN*NKV];
    __shared__ float sc[2][NN][NN];

    int s = blockIdx.x;
    int tid = threadIdx.x;
    size_t qb = (size_t)s*NN*EE;
    size_t kb = (size_t)s*NN*NKV;

    for (int i = tid; i < NN*EE;  i += 256) sq[i]  = qp[qb + i];
    for (int i = tid; i < NN*NKV; i += 256) skv[i] = kvp[kb + i];
    __syncthreads();

    if (tid < 2*NN*NN) {
        int h = tid / (NN*NN);
        int r = tid - h*NN*NN;
        int i = r / NN, j = r - i*NN;
        int off = h*HDIM;
        const float* q = sq  + i*EE  + off;
        const float* k = skv + j*NKV + off;
        float sum = 0.f;
        #pragma unroll 4
        for (int d = 0; d < HDIM; d++) sum = fmaf(q[d], k[d], sum);
        sc[h][i][j] = sum;
    }
    __syncthreads();

    if (tid < 2*NN) {
        int h = tid / NN, i = tid - h*NN;
        float m = -1e30f;
        #pragma unroll
        for (int j = 0; j < NN; j++) m = fmaxf(m, sc[h][i][j]);
        float ssum = 0.f;
        #pragma unroll
        for (int j = 0; j < NN; j++) {
            float e = expf(sc[h][i][j] - m);
            sc[h][i][j] = e;
            ssum += e;
        }
        float inv = 1.f / ssum;
        #pragma unroll
        for (int j = 0; j < NN; j++) sc[h][i][j] *= inv;
    }
    __syncthreads();

    for (int t = tid; t < NN*EE; t += 256) {
        int i = t / EE, col = t - i*EE;
        int h = (col >= HDIM) ? 1 : 0;
        float sum = 0.f;
        #pragma unroll
        for (int j = 0; j < NN; j++)
            sum = fmaf(sc[h][i][j], skv[j*NKV + EE + col], sum);
        out[qb + t] = sum;
    }
}

// ---------------- row softmax over 2048 (prop 1) ----------------
__global__ __launch_bounds__(256)
void softmax_k(float* __restrict__ p)
{
    __shared__ float red[8];
    size_t base = (size_t)blockIdx.x * 2048;
    int tid = threadIdx.x;

    float v[8];
    float m = -1e30f;
    #pragma unroll
    for (int u = 0; u < 8; u++) {
        v[u] = p[base + tid + u*256];
        m = fmaxf(m, v[u]);
    }
    #pragma unroll
    for (int o = 16; o; o >>= 1) m = fmaxf(m, __shfl_xor_sync(0xffffffffu, m, o));
    if ((tid & 31) == 0) red[tid >> 5] = m;
    __syncthreads();
    float mm = red[0];
    #pragma unroll
    for (int i = 1; i < 8; i++) mm = fmaxf(mm, red[i]);

    float s = 0.f;
    #pragma unroll
    for (int u = 0; u < 8; u++) {
        v[u] = __expf(v[u] - mm);
        s += v[u];
    }
    #pragma unroll
    for (int o = 16; o; o >>= 1) s += __shfl_xor_sync(0xffffffffu, s, o);
    __syncthreads();
    if ((tid & 31) == 0) red[tid >> 5] = s;
    __syncthreads();
    float tot = 0.f;
    #pragma unroll
    for (int i = 0; i < 8; i++) tot += red[i];
    float inv = 1.f / tot;
    #pragma unroll
    for (int u = 0; u < 8; u++) p[base + tid + u*256] = v[u] * inv;
}

// ---------------- transpose vp1 into [h*136+d][2048] ----------------
__global__ void transpose_v_k(const float* __restrict__ kvp, float* __restrict__ vT)
{
    int idx = blockIdx.x*256 + threadIdx.x;
    if (idx >= 2*HDIM*SZ) return;
    int j  = idx & 2047;
    int hd = idx >> 11;
    vT[idx] = kvp[(size_t)j*NKV + EE + hd];
}

// ---------------- launcher ----------------
extern "C" void kernel_launch(void* const* d_in, const int* in_sizes, int n_in,
                              void* d_out, int out_size)
{
    const float* emb0  = (const float*)d_in[0];
    const float* edge0 = (const float*)d_in[1];
    const float* td0   = (const float*)d_in[2];
    const float* emb1  = (const float*)d_in[3];
    const float* edge1 = (const float*)d_in[4];
    const float* td1   = (const float*)d_in[5];
    const float* emb2  = (const float*)d_in[6];
    const float* Wq = (const float*)d_in[7];
    const float* bq = (const float*)d_in[8];
    const float* Wk = (const float*)d_in[9];
    const float* bk = (const float*)d_in[10];
    const float* Wv = (const float*)d_in[11];
    const float* bv = (const float*)d_in[12];
    const float* Wo = (const float*)d_in[13];
    const float* bo = (const float*)d_in[14];
    const float* W1 = (const float*)d_in[15];
    const float* b1 = (const float*)d_in[16];
    const float* W2 = (const float*)d_in[17];
    const float* b2 = (const float*)d_in[18];
    float* out = (float*)d_out;

    float *qp0, *kvp0, *attn0, *a0, *h0;
    float *qp1, *kvp1, *scores, *vT, *attn1, *a1, *h1, *wkv, *bkv;
    cudaGetSymbolAddress((void**)&qp0,   g_qp0);
    cudaGetSymbolAddress((void**)&kvp0,  g_kvp0);
    cudaGetSymbolAddress((void**)&attn0, g_attn0);
    cudaGetSymbolAddress((void**)&a0,    g_a0);
    cudaGetSymbolAddress((void**)&h0,    g_h0);
    cudaGetSymbolAddress((void**)&qp1,   g_qp1);
    cudaGetSymbolAddress((void**)&kvp1,  g_kvp1);
    cudaGetSymbolAddress((void**)&scores,g_scores);
    cudaGetSymbolAddress((void**)&vT,    g_vT);
    cudaGetSymbolAddress((void**)&attn1, g_attn1);
    cudaGetSymbolAddress((void**)&a1,    g_a1);
    cudaGetSymbolAddress((void**)&h1,    g_h1);
    cudaGetSymbolAddress((void**)&wkv,   g_Wkv);
    cudaGetSymbolAddress((void**)&bkv,   g_bkv);

    const float SCALE = 0.08574929257125441f;  // 1/sqrt(136)

    pack_wkv_k<<<cdiv(NKV*KDT, 256), 256>>>(Wk, Wv, bk, bv);

    // ======== propagation 0 ========
    tgemm_k<2><<<dim3(cdiv(EE,64), cdiv(M0,128)), 256>>>(
        emb1, td1, nullptr, 0, 0, Wq, EE, 0, bq, qp0, EE, 0, M0, EE, EE, SCALE, 0);
    tgemm_wide<1><<<dim3(cdiv(NKV,128), cdiv(M0,128)), 256>>>(
        emb0, edge0, td0, 0, 0, wkv, KDT, 0, bkv, kvp0, NKV, 0, M0, NKV, KDT, 1.f);
    attn0_k<<<SZ, 256>>>(qp0, kvp0, attn0);
    tgemm_k<0><<<dim3(cdiv(EE,64), cdiv(M0,128)), 256>>>(
        attn0, nullptr, nullptr, EE, 0, Wo, EE, 0, bo, a0, EE, 0, M0, EE, EE, 1.f, 0);
    tgemm_k<3><<<dim3(cdiv(DD,64), cdiv(M0,128)), 256>>>(
        a0, emb1, nullptr, 0, 0, W1, KDIM, 0, b1, h0, DD, 0, M0, DD, KDIM, 1.f, 1);
    tgemm_k<0><<<dim3(cdiv(DD,64), cdiv(M0,128)), 256>>>(
        h0, nullptr, nullptr, DD, 0, W2, DD, 0, b2, out + OUT_R0, DD, 0, M0, DD, DD, 1.f, 0);

    // ======== propagation 1 ========
    tgemm_k<2><<<dim3(cdiv(EE,64), cdiv(SZ,128)), 256>>>(
        emb2, nullptr, nullptr, 0, 0, Wq, EE, 0, bq, qp1, EE, 0, SZ, EE, EE, SCALE, 0);
    tgemm_wide<1><<<dim3(cdiv(NKV,128), cdiv(SZ,128)), 256>>>(
        emb1, edge1, td1, 0, 0, wkv, KDT, 0, bkv, kvp1, NKV, 0, SZ, NKV, KDT, 1.f);
    for (int h = 0; h < 2; h++) {
        tgemm_wide<0><<<dim3(cdiv(SZ,128), cdiv(SZ,128)), 256>>>(
            qp1, nullptr, nullptr, EE, h*HDIM, kvp1, NKV, h*HDIM, nullptr,
            scores + (size_t)h*SZ*SZ, SZ, 0, SZ, SZ, HDIM, 1.f);
    }
    softmax_k<<<2*SZ, 256>>>(scores);
    transpose_v_k<<<cdiv(2*HDIM*SZ, 256), 256>>>(kvp1, vT);
    for (int h = 0; h < 2; h++) {
        tgemm_k<0><<<dim3(cdiv(HDIM,64), cdiv(SZ,128)), 256>>>(
            scores + (size_t)h*SZ*SZ, nullptr, nullptr, SZ, 0,
            vT + (size_t)h*HDIM*SZ, SZ, 0, nullptr,
            attn1, EE, h*HDIM, SZ, HDIM, SZ, 1.f, 0);
    }
    tgemm_k<0><<<dim3(cdiv(EE,64), cdiv(SZ,128)), 256>>>(
        attn1, nullptr, nullptr, EE, 0, Wo, EE, 0, bo, a1, EE, 0, SZ, EE, EE, 1.f, 0);
    tgemm_k<3><<<dim3(cdiv(DD,64), cdiv(SZ,128)), 256>>>(
        a1, emb2, nullptr, 0, 0, W1, KDIM, 0, b1, h1, DD, 0, SZ, DD, KDIM, 1.f, 1);
    tgemm_k<0><<<dim3(cdiv(DD,64), cdiv(SZ,128)), 256>>>(
        h1, nullptr, nullptr, DD, 0, W2, DD, 0, b2, out + OUT_R1, DD, 0, SZ, DD, DD, 1.f, 0);

    // ======== pass-through outputs ========
    cudaMemcpyAsync(out + OUT_E1, edge1, (size_t)SZ*NN*EDGE_*sizeof(float),
                    cudaMemcpyDeviceToDevice);
    cudaMemcpyAsync(out + OUT_T1, td1, (size_t)SZ*NN*TDIM*sizeof(float),
                    cudaMemcpyDeviceToDevice);
}